// round 2
// baseline (speedup 1.0000x reference)
#include <cuda_runtime.h>

#define B_   8
#define S_   4096
#define D_   1024
#define ROWS (B_ * S_)      // 32768
#define VEC  (D_ / 4)       // 256 float4 per row

// Scratch (allocations are forbidden): per-position source row, mask-dtype flag.
__device__ int g_srcrow[ROWS];
__device__ int g_maskdtype;   // 0 = int32, 1 = uint8/bool, 2 = float32

// ---------------------------------------------------------------------------
// Detect how the harness serialized the bool mask. Reads the first 8192
// 32-bit words (= 32768 bytes), in-bounds for every candidate dtype
// (u8 buffer is exactly 32768 B; i32/f32 buffers are 131072 B).
//   u8 0/1 bytes -> packed words like 0x00010001 (>1, not the f32 pattern)
//   i32 0/1      -> all words in {0,1}
//   f32 0.0/1.0  -> words in {0, 0x3F800000}
// Deterministic: overwrites g_maskdtype unconditionally every launch.
// ---------------------------------------------------------------------------
__global__ void detect_mask_dtype(const unsigned int* __restrict__ w, int nwords) {
    __shared__ int sflag;
    if (threadIdx.x == 0) sflag = 0;
    __syncthreads();
    int f = 0;
    for (int i = threadIdx.x; i < nwords; i += blockDim.x) {
        unsigned int v = w[i];
        if (v == 0x3F800000u)      f = (f < 2) ? 2 : f;
        else if (v > 1u)           f = (f < 1) ? 1 : f;
    }
    atomicMax(&sflag, f);
    __syncthreads();
    if (threadIdx.x == 0) g_maskdtype = sflag;
}

// ---------------------------------------------------------------------------
// Per-batch-row inclusive cumsum of the boundary mask; emit, for each (b,s),
// the flattened source row (b*S + cum-1) or -1 when cum==0.
// One block per batch row; 512 threads x 8 elements each.
// ---------------------------------------------------------------------------
__global__ void scan_mask(const void* __restrict__ mask) {
    __shared__ int sh[512];
    const int b = blockIdx.x;
    const int t = threadIdx.x;
    const int PER = S_ / 512;           // 8
    const int dt = g_maskdtype;
    const int base = b * S_ + t * PER;

    int m[PER];
#pragma unroll
    for (int i = 0; i < PER; ++i) {
        const int idx = base + i;
        int v;
        if (dt == 1)      v = (((const unsigned char*)mask)[idx] != 0);
        else if (dt == 2) v = (((const float*)mask)[idx] != 0.0f);
        else              v = (((const int*)mask)[idx] != 0);
        m[i] = v;
    }

    // thread-local inclusive prefix
    int run = 0;
#pragma unroll
    for (int i = 0; i < PER; ++i) { run += m[i]; m[i] = run; }

    sh[t] = run;
    __syncthreads();
    // Hillis-Steele inclusive scan over 512 partials
    for (int off = 1; off < 512; off <<= 1) {
        int v = (t >= off) ? sh[t - off] : 0;
        __syncthreads();
        sh[t] += v;
        __syncthreads();
    }
    const int excl = sh[t] - run;

#pragma unroll
    for (int i = 0; i < PER; ++i) {
        const int cum = excl + m[i];
        g_srcrow[base + i] = (cum > 0) ? (b * S_ + cum - 1) : -1;
    }
}

// ---------------------------------------------------------------------------
// out[row, :] = src>=0 ? states[src, :] : 0.
// One block (128 threads) per row; each thread moves two float4 (32 B) with
// independent loads (MLP=2). 32768 blocks saturate HBM across 148 SMs.
// Consecutive rows usually share a source row -> reads mostly hit L2.
// ---------------------------------------------------------------------------
__global__ void gather_rows(const float4* __restrict__ in, float4* __restrict__ out) {
    const int row = blockIdx.x;
    const int src = g_srcrow[row];
    const int t   = threadIdx.x;
    const long obase = (long)row * VEC;
    if (src >= 0) {
        const long ibase = (long)src * VEC;
        float4 v0 = __ldg(&in[ibase + t]);
        float4 v1 = __ldg(&in[ibase + t + 128]);
        out[obase + t]       = v0;
        out[obase + t + 128] = v1;
    } else {
        const float4 z = make_float4(0.f, 0.f, 0.f, 0.f);
        out[obase + t]       = z;
        out[obase + t + 128] = z;
    }
}

extern "C" void kernel_launch(void* const* d_in, const int* in_sizes, int n_in,
                              void* d_out, int out_size) {
    // Identify inputs by element count (robust to metadata ordering):
    //   states: 8*4096*1024 = 33554432, prob: 65536 (unused), mask: 32768
    const void* states = d_in[0];
    const void* mask   = d_in[n_in - 1];
    for (int i = 0; i < n_in; ++i) {
        if (in_sizes[i] == B_ * S_ * D_) states = d_in[i];
        else if (in_sizes[i] == B_ * S_) mask = d_in[i];
    }

    detect_mask_dtype<<<1, 1024>>>((const unsigned int*)mask, (B_ * S_) / 4);
    scan_mask<<<B_, 512>>>(mask);
    gather_rows<<<ROWS, 128>>>((const float4*)states, (float4*)d_out);
}

// round 3
// speedup vs baseline: 1.1288x; 1.1288x over previous
#include <cuda_runtime.h>

#define B_   8
#define S_   4096
#define D_   1024
#define ROWS (B_ * S_)      // 32768
#define VEC  (D_ / 4)       // 256 float4 per row

// Scratch (allocations are forbidden): per-position source row index.
__device__ int g_srcrow[ROWS];

// ---------------------------------------------------------------------------
// Fused dtype-detect + per-batch-row inclusive cumsum of the boundary mask.
//
// Dtype detection (per block, no extra kernel): read the first 8192 32-bit
// words (= 32768 bytes; in-bounds for u8 [exactly 32768 B] and i32/f32
// [131072 B]) and classify:
//   u8 0/1 bytes -> packed words like 0x00010001 (>1, can never equal the
//                   f32 pattern: 0x3F800000 has bytes 0x3F/0x80)
//   i32 0/1      -> all words in {0,1}
//   f32 0.0/1.0  -> words in {0, 0x3F800000}
// Block 0 pays one cold DRAM pass; blocks 1..7 hit L2. Deterministic.
//
// Then: one block per batch row; 512 threads x 8 elements; emit for each
// (b,s) the flattened source row (b*S + cum-1), or -1 when cum==0.
// ---------------------------------------------------------------------------
__global__ void scan_mask(const void* __restrict__ mask) {
    __shared__ int sh[512];
    __shared__ int sdt;
    const int b = blockIdx.x;
    const int t = threadIdx.x;

    // --- dtype detection ---
    if (t == 0) sdt = 0;
    __syncthreads();
    {
        const unsigned int* w = (const unsigned int*)mask;
        int f = 0;
        #pragma unroll
        for (int i = 0; i < 16; ++i) {           // 16 * 512 = 8192 words
            unsigned int v = __ldg(&w[t + i * 512]);
            if (v == 0x3F800000u)      f = (f < 2) ? 2 : f;
            else if (v > 1u)           f = (f < 1) ? 1 : f;
        }
        if (f) atomicMax(&sdt, f);
    }
    __syncthreads();
    const int dt = sdt;   // 0 = int32, 1 = uint8/bool, 2 = float32

    // --- load this batch row's mask slice ---
    const int PER = S_ / 512;           // 8
    const int base = b * S_ + t * PER;
    int m[PER];
#pragma unroll
    for (int i = 0; i < PER; ++i) {
        const int idx = base + i;
        int v;
        if (dt == 1)      v = (((const unsigned char*)mask)[idx] != 0);
        else if (dt == 2) v = (((const float*)mask)[idx] != 0.0f);
        else              v = (((const int*)mask)[idx] != 0);
        m[i] = v;
    }

    // thread-local inclusive prefix
    int run = 0;
#pragma unroll
    for (int i = 0; i < PER; ++i) { run += m[i]; m[i] = run; }

    sh[t] = run;
    __syncthreads();
    // Hillis-Steele inclusive scan over 512 partials
    for (int off = 1; off < 512; off <<= 1) {
        int v = (t >= off) ? sh[t - off] : 0;
        __syncthreads();
        sh[t] += v;
        __syncthreads();
    }
    const int excl = sh[t] - run;

#pragma unroll
    for (int i = 0; i < PER; ++i) {
        const int cum = excl + m[i];
        g_srcrow[base + i] = (cum > 0) ? (b * S_ + cum - 1) : -1;
    }
}

// ---------------------------------------------------------------------------
// out[row, :] = src>=0 ? states[src, :] : 0.
// One block (128 threads) per row; each thread moves two float4 (32 B) with
// independent loads (MLP=2). Streaming (evict-first) stores keep the
// write-once output from evicting cached source rows: consecutive rows
// usually share a source (avg segment ~2), so reads mostly hit L2.
// ---------------------------------------------------------------------------
__global__ void gather_rows(const float4* __restrict__ in, float4* __restrict__ out) {
    const int row = blockIdx.x;
    const int src = g_srcrow[row];
    const int t   = threadIdx.x;
    const long obase = (long)row * VEC;
    if (src >= 0) {
        const long ibase = (long)src * VEC;
        float4 v0 = __ldg(&in[ibase + t]);
        float4 v1 = __ldg(&in[ibase + t + 128]);
        __stcs(&out[obase + t],       v0);
        __stcs(&out[obase + t + 128], v1);
    } else {
        const float4 z = make_float4(0.f, 0.f, 0.f, 0.f);
        __stcs(&out[obase + t],       z);
        __stcs(&out[obase + t + 128], z);
    }
}

extern "C" void kernel_launch(void* const* d_in, const int* in_sizes, int n_in,
                              void* d_out, int out_size) {
    // Identify inputs by element count (robust to metadata ordering):
    //   states: 8*4096*1024 = 33554432, prob: 65536 (unused), mask: 32768
    const void* states = d_in[0];
    const void* mask   = d_in[n_in - 1];
    for (int i = 0; i < n_in; ++i) {
        if (in_sizes[i] == B_ * S_ * D_) states = d_in[i];
        else if (in_sizes[i] == B_ * S_) mask = d_in[i];
    }

    scan_mask<<<B_, 512>>>(mask);
    gather_rows<<<ROWS, 128>>>((const float4*)states, (float4*)d_out);
}

// round 4
// speedup vs baseline: 1.1683x; 1.0349x over previous
#include <cuda_runtime.h>

#define B_   8
#define S_   4096
#define D_   1024
#define ROWS (B_ * S_)      // 32768
#define VEC  (D_ / 4)       // 256 float4 per row

// Scratch (allocations are forbidden): per-position source row index.
__device__ int g_srcrow[ROWS];

// ---------------------------------------------------------------------------
// Fused dtype-detect + per-batch-row inclusive cumsum of the boundary mask.
// One block (1024 threads) per batch row; 4 elements per thread; shuffle-based
// scan (3 barriers total instead of 18).
//
// Dtype detection: read the first 8192 32-bit words (= 32768 bytes; in-bounds
// for u8 [exactly 32768 B] and i32/f32 [131072 B]) and classify:
//   u8 0/1 bytes -> packed words like 0x00010001 (>1, never the f32 pattern)
//   i32 0/1      -> all words in {0,1}
//   f32 0.0/1.0  -> words in {0, 0x3F800000}
// ---------------------------------------------------------------------------
__global__ __launch_bounds__(1024) void scan_mask(const void* __restrict__ mask) {
    __shared__ int warp_tot[32];
    __shared__ int sdt;
    const int b    = blockIdx.x;
    const int t    = threadIdx.x;
    const int lane = t & 31;
    const int wid  = t >> 5;

    if (t == 0) sdt = 0;
    __syncthreads();

    // --- dtype detection: 8 independent LDGs per thread ---
    {
        const unsigned int* w = (const unsigned int*)mask;
        int f = 0;
        #pragma unroll
        for (int i = 0; i < 8; ++i) {            // 8 * 1024 = 8192 words
            unsigned int v = __ldg(&w[t + i * 1024]);
            if (v == 0x3F800000u)      f = (f < 2) ? 2 : f;
            else if (v > 1u)           f = (f < 1) ? 1 : f;
        }
        if (f) atomicMax(&sdt, f);
    }
    __syncthreads();
    const int dt = sdt;   // 0 = int32, 1 = uint8/bool, 2 = float32

    // --- load this batch row's mask slice: 4 elements per thread ---
    const int PER  = S_ / 1024;          // 4
    const int base = b * S_ + t * PER;
    int m[PER];
#pragma unroll
    for (int i = 0; i < PER; ++i) {
        const int idx = base + i;
        int v;
        if (dt == 1)      v = (((const unsigned char*)mask)[idx] != 0);
        else if (dt == 2) v = (((const float*)mask)[idx] != 0.0f);
        else              v = (((const int*)mask)[idx] != 0);
        m[i] = v;
    }

    // thread-local inclusive prefix
    int run = 0;
#pragma unroll
    for (int i = 0; i < PER; ++i) { run += m[i]; m[i] = run; }

    // warp-inclusive scan of per-thread totals
    int v = run;
#pragma unroll
    for (int off = 1; off < 32; off <<= 1) {
        int u = __shfl_up_sync(0xFFFFFFFFu, v, off);
        if (lane >= off) v += u;
    }
    if (lane == 31) warp_tot[wid] = v;
    __syncthreads();

    // warp 0 scans the 32 warp totals (inclusive)
    if (wid == 0) {
        int w = warp_tot[lane];
#pragma unroll
        for (int off = 1; off < 32; off <<= 1) {
            int u = __shfl_up_sync(0xFFFFFFFFu, w, off);
            if (lane >= off) w += u;
        }
        warp_tot[lane] = w;
    }
    __syncthreads();

    const int excl = (v - run) + (wid > 0 ? warp_tot[wid - 1] : 0);

#pragma unroll
    for (int i = 0; i < PER; ++i) {
        const int cum = excl + m[i];
        g_srcrow[base + i] = (cum > 0) ? (b * S_ + cum - 1) : -1;
    }
}

// ---------------------------------------------------------------------------
// out[row, :] = src>=0 ? states[src, :] : 0.
// 256-thread blocks, 4 rows per block (grid = 8192). Each thread issues 4
// independent 16B loads (ptxas front-batches them -> MLP=4) and 4 streaming
// stores. Streaming stores keep the write-once output from evicting cached
// source rows (adjacent rows usually share a source -> read-side L2 hits).
// ---------------------------------------------------------------------------
__global__ __launch_bounds__(256) void gather_rows(const float4* __restrict__ in,
                                                   float4* __restrict__ out) {
    const int rbase = blockIdx.x * 4;
    const int t     = threadIdx.x;

    const int s0 = g_srcrow[rbase + 0];
    const int s1 = g_srcrow[rbase + 1];
    const int s2 = g_srcrow[rbase + 2];
    const int s3 = g_srcrow[rbase + 3];

    const float4 z = make_float4(0.f, 0.f, 0.f, 0.f);
    float4 v0 = z, v1 = z, v2 = z, v3 = z;
    if (s0 >= 0) v0 = __ldg(&in[s0 * VEC + t]);
    if (s1 >= 0) v1 = __ldg(&in[s1 * VEC + t]);
    if (s2 >= 0) v2 = __ldg(&in[s2 * VEC + t]);
    if (s3 >= 0) v3 = __ldg(&in[s3 * VEC + t]);

    float4* o = out + (long)rbase * VEC + t;
    __stcs(o + 0 * VEC, v0);
    __stcs(o + 1 * VEC, v1);
    __stcs(o + 2 * VEC, v2);
    __stcs(o + 3 * VEC, v3);
}

extern "C" void kernel_launch(void* const* d_in, const int* in_sizes, int n_in,
                              void* d_out, int out_size) {
    // Identify inputs by element count (robust to metadata ordering):
    //   states: 8*4096*1024 = 33554432, prob: 65536 (unused), mask: 32768
    const void* states = d_in[0];
    const void* mask   = d_in[n_in - 1];
    for (int i = 0; i < n_in; ++i) {
        if (in_sizes[i] == B_ * S_ * D_) states = d_in[i];
        else if (in_sizes[i] == B_ * S_) mask = d_in[i];
    }

    scan_mask<<<B_, 1024>>>(mask);
    gather_rows<<<ROWS / 4, 256>>>((const float4*)states, (float4*)d_out);
}

// round 5
// speedup vs baseline: 1.1958x; 1.0236x over previous
#include <cuda_runtime.h>

#define B_   8
#define S_   4096
#define D_   1024
#define ROWS (B_ * S_)      // 32768
#define VEC  (D_ / 4)       // 256 float4 per row

// Scratch (allocations are forbidden): per-position source row index.
__device__ __align__(32) int g_srcrow[ROWS];

// ---------------------------------------------------------------------------
// Fused dtype-detect + per-batch-row inclusive cumsum of the boundary mask.
// One block (1024 threads) per batch row; 4 elements per thread; shuffle scan.
//
// Dtype detection: 1 word per thread over the first 1024 32-bit words
// (= 4096 bytes, in-bounds for every candidate dtype):
//   u8 0/1 bytes -> words like 0x00010001 (>1; a word is in {0,1} only with
//                   prob 1/8, so 1024 words misclassify with prob 8^-1024)
//   i32 0/1      -> all words in {0,1}
//   f32 0.0/1.0  -> words in {0, 0x3F800000}
// Mask decode then uses ONE wide load per thread (u32 / int4 / float4).
// ---------------------------------------------------------------------------
__global__ __launch_bounds__(1024) void scan_mask(const void* __restrict__ mask) {
    __shared__ int warp_tot[32];
    __shared__ int sdt;
    const int b    = blockIdx.x;
    const int t    = threadIdx.x;
    const int lane = t & 31;
    const int wid  = t >> 5;

    if (t == 0) sdt = 0;
    __syncthreads();

    // --- dtype detection: 1 LDG per thread ---
    {
        const unsigned int v = __ldg(&((const unsigned int*)mask)[t]);
        int f = 0;
        if (v == 0x3F800000u)      f = 2;
        else if (v > 1u)           f = 1;
        if (f) atomicMax(&sdt, f);
    }
    __syncthreads();
    const int dt = sdt;   // 0 = int32, 1 = uint8/bool, 2 = float32

    // --- load this batch row's 4-element mask slice with ONE wide load ---
    const int base = b * S_ + t * 4;
    int m[4];
    if (dt == 1) {
        const unsigned int w = __ldg(&((const unsigned int*)mask)[base >> 2]);
        m[0] = ( w        & 0xFFu) != 0;
        m[1] = ((w >>  8) & 0xFFu) != 0;
        m[2] = ((w >> 16) & 0xFFu) != 0;
        m[3] = ((w >> 24) & 0xFFu) != 0;
    } else if (dt == 2) {
        const float4 w = __ldg(&((const float4*)mask)[base >> 2]);
        m[0] = (w.x != 0.0f); m[1] = (w.y != 0.0f);
        m[2] = (w.z != 0.0f); m[3] = (w.w != 0.0f);
    } else {
        const int4 w = __ldg(&((const int4*)mask)[base >> 2]);
        m[0] = (w.x != 0); m[1] = (w.y != 0);
        m[2] = (w.z != 0); m[3] = (w.w != 0);
    }

    // thread-local inclusive prefix
    int run = 0;
#pragma unroll
    for (int i = 0; i < 4; ++i) { run += m[i]; m[i] = run; }

    // warp-inclusive scan of per-thread totals
    int v = run;
#pragma unroll
    for (int off = 1; off < 32; off <<= 1) {
        int u = __shfl_up_sync(0xFFFFFFFFu, v, off);
        if (lane >= off) v += u;
    }
    if (lane == 31) warp_tot[wid] = v;
    __syncthreads();

    // warp 0 scans the 32 warp totals (inclusive)
    if (wid == 0) {
        int w = warp_tot[lane];
#pragma unroll
        for (int off = 1; off < 32; off <<= 1) {
            int u = __shfl_up_sync(0xFFFFFFFFu, w, off);
            if (lane >= off) w += u;
        }
        warp_tot[lane] = w;
    }
    __syncthreads();

    const int excl = (v - run) + (wid > 0 ? warp_tot[wid - 1] : 0);

#pragma unroll
    for (int i = 0; i < 4; ++i) {
        const int cum = excl + m[i];
        g_srcrow[base + i] = (cum > 0) ? (b * S_ + cum - 1) : -1;
    }
}

// ---------------------------------------------------------------------------
// out[row, :] = src>=0 ? states[src, :] : 0.
// 256-thread blocks, 8 rows per block (grid = 4096). Each thread front-
// batches 8 independent 16B loads (MLP=8, 128 B in flight) then 8 streaming
// stores. Consecutive rows usually share a source -> loads hit L1/L2.
// Streaming stores keep the write-once output from evicting cached sources.
// ---------------------------------------------------------------------------
__global__ __launch_bounds__(256) void gather_rows(const float4* __restrict__ in,
                                                   float4* __restrict__ out) {
    const int rbase = blockIdx.x * 8;
    const int t     = threadIdx.x;

    const int4 sa = *(const int4*)&g_srcrow[rbase];
    const int4 sb = *(const int4*)&g_srcrow[rbase + 4];
    const int s[8] = { sa.x, sa.y, sa.z, sa.w, sb.x, sb.y, sb.z, sb.w };

    const float4 z = make_float4(0.f, 0.f, 0.f, 0.f);
    float4 v[8];
#pragma unroll
    for (int i = 0; i < 8; ++i)
        v[i] = (s[i] >= 0) ? __ldg(&in[s[i] * VEC + t]) : z;

    float4* o = out + (long)rbase * VEC + t;
#pragma unroll
    for (int i = 0; i < 8; ++i)
        __stcs(o + i * VEC, v[i]);
}

extern "C" void kernel_launch(void* const* d_in, const int* in_sizes, int n_in,
                              void* d_out, int out_size) {
    // Identify inputs by element count (robust to metadata ordering):
    //   states: 8*4096*1024 = 33554432, prob: 65536 (unused), mask: 32768
    const void* states = d_in[0];
    const void* mask   = d_in[n_in - 1];
    for (int i = 0; i < n_in; ++i) {
        if (in_sizes[i] == B_ * S_ * D_) states = d_in[i];
        else if (in_sizes[i] == B_ * S_) mask = d_in[i];
    }

    scan_mask<<<B_, 1024>>>(mask);
    gather_rows<<<ROWS / 8, 256>>>((const float4*)states, (float4*)d_out);
}